// round 2
// baseline (speedup 1.0000x reference)
#include <cuda_runtime.h>
#include <cuda_bf16.h>
#include <math.h>

// SupConLoss fused: normalize -> triangular tiled Gram (fp32 FFMA) with fused
// exp/mask epilogue -> per-row scalar accum via atomics -> final reduce.
//
// Per row i:  loss_i = log(S_i + 1e-9) - P_i / n_pos_i   (0 if n_pos_i == 0)
//   S_i = sum_{j!=i} exp(sim_ij),  P_i = sum_{j!=i, lab_j==lab_i} sim_ij
//   n_pos_i = labcount[lab_i] - 1
// loss = mean_i loss_i

#define MAXN 8192
#define D128 128
#define INV_T 10.0f

__device__ float g_feats[MAXN * D128];
__device__ float g_sumexp[MAXN];
__device__ float g_psum[MAXN];
__device__ int   g_labcnt[1024];
__device__ int   g_lab64;   // 1 if labels buffer is int64, 0 if int32

__device__ __forceinline__ int load_lab(const int* labw, int i, int is64) {
    return labw[is64 ? (i << 1) : i];
}

// ---------------------------------------------------------------------------
// K0: zero accumulators + detect label dtype (int64 high words all zero)
// ---------------------------------------------------------------------------
__global__ void k_init(const int* __restrict__ labw, int N) {
    int tid = blockIdx.x * blockDim.x + threadIdx.x;
    int stride = gridDim.x * blockDim.x;
    for (int i = tid; i < N; i += stride) { g_sumexp[i] = 0.0f; g_psum[i] = 0.0f; }
    for (int i = tid; i < 1024; i += stride) g_labcnt[i] = 0;
    if (blockIdx.x == 0 && threadIdx.x == 0) {
        // Safe for both dtypes: reads words [0, 63] < N words.
        int z = 0;
        #pragma unroll
        for (int i = 0; i < 32; ++i) z |= labw[2 * i + 1];
        g_lab64 = (z == 0) ? 1 : 0;
    }
}

// ---------------------------------------------------------------------------
// K1: L2-normalize rows (one warp per row) + label histogram
// ---------------------------------------------------------------------------
__global__ void k_norm(const float* __restrict__ feats,
                       const int* __restrict__ labw, int N) {
    int row = blockIdx.x * 8 + (threadIdx.x >> 5);
    int lane = threadIdx.x & 31;
    if (row >= N) return;
    const float4 v = *(const float4*)(feats + row * D128 + (lane << 2));
    float ss = v.x * v.x + v.y * v.y + v.z * v.z + v.w * v.w;
    #pragma unroll
    for (int o = 16; o > 0; o >>= 1) ss += __shfl_xor_sync(0xFFFFFFFFu, ss, o);
    float inv = rsqrtf(ss);
    float4 o4 = make_float4(v.x * inv, v.y * inv, v.z * inv, v.w * inv);
    *(float4*)(g_feats + row * D128 + (lane << 2)) = o4;
    if (lane == 0) atomicAdd(&g_labcnt[load_lab(labw, row, g_lab64) & 1023], 1);
}

// ---------------------------------------------------------------------------
// K2: triangular 128x128 Gram tiles, fused epilogue
// Shared layout: k-major [128][128] with group swizzle: group g=m>>2 stored at
// g ^ ((k>>2)&31).  Conflict-free STS-transpose writes AND float4 LDS reads.
// ---------------------------------------------------------------------------
#define SMEM_FLOATS (2 * 16384)
#define SMEM_BYTES  (SMEM_FLOATS * 4 + 256 * 4)

__global__ void __launch_bounds__(256, 1)
k_gemm(const int* __restrict__ labw) {
    extern __shared__ float sm[];
    float* As = sm;
    float* Bs = sm + 16384;
    int* labA = (int*)(sm + 32768);
    int* labB = labA + 128;

    const int bx = blockIdx.x, by = blockIdx.y;
    if (by > bx) return;                       // triangular: rows-tile by <= cols-tile bx
    const int m0 = by << 7, n0 = bx << 7;
    const int tid = threadIdx.x;
    const int is64 = g_lab64;

    if (tid < 128) labA[tid] = load_lab(labw, m0 + tid, is64);
    else           labB[tid - 128] = load_lab(labw, n0 + tid - 128, is64);

    // Load both 128x128 tiles (full K), transposing to k-major with swizzle.
    #pragma unroll
    for (int it = 0; it < 16; ++it) {
        int idx = (it << 8) + tid;      // 0..4095
        int m  = idx >> 5;              // row within tile
        int k4 = idx & 31;              // float4 index along k
        const float4 va = *(const float4*)(g_feats + (m0 + m) * D128 + (k4 << 2));
        const float4 vb = *(const float4*)(g_feats + (n0 + m) * D128 + (k4 << 2));
        int col = ((((m >> 2) ^ k4) << 2) | (m & 3));
        float* pa = As + (k4 << 9);     // k0*128, k0 = 4*k4
        pa[col] = va.x; pa[128 + col] = va.y; pa[256 + col] = va.z; pa[384 + col] = va.w;
        float* pb = Bs + (k4 << 9);
        pb[col] = vb.x; pb[128 + col] = vb.y; pb[256 + col] = vb.z; pb[384 + col] = vb.w;
    }
    __syncthreads();

    const int tx = tid & 15, ty = tid >> 4;
    float acc[8][8];
    #pragma unroll
    for (int r = 0; r < 8; ++r)
        #pragma unroll
        for (int c = 0; c < 8; ++c) acc[r][c] = 0.0f;

    #pragma unroll 4
    for (int k = 0; k < 128; ++k) {
        int kk = k >> 2;
        const float* ak = As + (k << 7);
        const float* bk = Bs + (k << 7);
        const float4 a0 = *(const float4*)(ak + ((((ty << 1)     ) ^ kk) << 2));
        const float4 a1 = *(const float4*)(ak + ((((ty << 1) | 1 ) ^ kk) << 2));
        const float4 b0 = *(const float4*)(bk + ((((tx << 1)     ) ^ kk) << 2));
        const float4 b1 = *(const float4*)(bk + ((((tx << 1) | 1 ) ^ kk) << 2));
        float a[8] = {a0.x, a0.y, a0.z, a0.w, a1.x, a1.y, a1.z, a1.w};
        float b[8] = {b0.x, b0.y, b0.z, b0.w, b1.x, b1.y, b1.z, b1.w};
        #pragma unroll
        for (int r = 0; r < 8; ++r)
            #pragma unroll
            for (int c = 0; c < 8; ++c)
                acc[r][c] = fmaf(a[r], b[c], acc[r][c]);
    }

    // ---- fused epilogue ----
    const bool diag = (bx == by);
    float rs[8], rp[8], cs[8], cp[8];
    int mylab[8], nlab[8];
    #pragma unroll
    for (int r = 0; r < 8; ++r) { rs[r] = 0; rp[r] = 0; mylab[r] = labA[(ty << 3) + r]; }
    #pragma unroll
    for (int c = 0; c < 8; ++c) { cs[c] = 0; cp[c] = 0; nlab[c] = labB[(tx << 3) + c]; }

    #pragma unroll
    for (int r = 0; r < 8; ++r) {
        int gi = m0 + (ty << 3) + r;
        #pragma unroll
        for (int c = 0; c < 8; ++c) {
            int gj = n0 + (tx << 3) + c;
            if (gi == gj) continue;            // exclude diagonal (diag blocks only)
            float v = acc[r][c] * INV_T;
            float e = __expf(v);
            bool match = (mylab[r] == nlab[c]);
            rs[r] += e;
            cs[c] += e;
            if (match) { rp[r] += v; cp[c] += v; }
        }
    }

    __syncthreads();                 // tiles no longer needed; reuse As as red buf
    float* red = sm;                 // [16][132]
    // rows: reduce over tx -> rows m0 + m
    #pragma unroll
    for (int r = 0; r < 8; ++r) red[tx * 132 + (ty << 3) + r] = rs[r];
    __syncthreads();
    if (tid < 128) {
        float s = 0;
        #pragma unroll
        for (int j = 0; j < 16; ++j) s += red[j * 132 + tid];
        atomicAdd(&g_sumexp[m0 + tid], s);
    }
    __syncthreads();
    #pragma unroll
    for (int r = 0; r < 8; ++r) red[tx * 132 + (ty << 3) + r] = rp[r];
    __syncthreads();
    if (tid < 128) {
        float s = 0;
        #pragma unroll
        for (int j = 0; j < 16; ++j) s += red[j * 132 + tid];
        atomicAdd(&g_psum[m0 + tid], s);
    }
    if (!diag) {   // symmetric contribution: cols of this tile are rows n0 + n
        __syncthreads();
        #pragma unroll
        for (int c = 0; c < 8; ++c) red[ty * 132 + (tx << 3) + c] = cs[c];
        __syncthreads();
        if (tid < 128) {
            float s = 0;
            #pragma unroll
            for (int j = 0; j < 16; ++j) s += red[j * 132 + tid];
            atomicAdd(&g_sumexp[n0 + tid], s);
        }
        __syncthreads();
        #pragma unroll
        for (int c = 0; c < 8; ++c) red[ty * 132 + (tx << 3) + c] = cp[c];
        __syncthreads();
        if (tid < 128) {
            float s = 0;
            #pragma unroll
            for (int j = 0; j < 16; ++j) s += red[j * 132 + tid];
            atomicAdd(&g_psum[n0 + tid], s);
        }
    }
}

// ---------------------------------------------------------------------------
// K3: final reduction -> scalar loss
// ---------------------------------------------------------------------------
__global__ void k_final(const int* __restrict__ labw, float* __restrict__ out, int N) {
    __shared__ float wsum[32];
    const int tid = threadIdx.x;
    const int is64 = g_lab64;
    float local = 0.0f;
    for (int i = tid; i < N; i += blockDim.x) {
        int lab = load_lab(labw, i, is64) & 1023;
        int np = g_labcnt[lab] - 1;
        if (np > 0) {
            float L = logf(g_sumexp[i] + 1e-9f);
            local += L - g_psum[i] / (float)np;
        }
    }
    #pragma unroll
    for (int o = 16; o > 0; o >>= 1) local += __shfl_xor_sync(0xFFFFFFFFu, local, o);
    if ((tid & 31) == 0) wsum[tid >> 5] = local;
    __syncthreads();
    if (tid < 32) {
        float v = (tid < (blockDim.x >> 5)) ? wsum[tid] : 0.0f;
        #pragma unroll
        for (int o = 16; o > 0; o >>= 1) v += __shfl_xor_sync(0xFFFFFFFFu, v, o);
        if (tid == 0) out[0] = v / (float)N;
    }
}

// ---------------------------------------------------------------------------
extern "C" void kernel_launch(void* const* d_in, const int* in_sizes, int n_in,
                              void* d_out, int out_size) {
    const float* feats = (const float*)d_in[0];
    const int*   labw  = (const int*)d_in[1];   // int32 or int64 words; auto-detected
    const int N = in_sizes[1];
    const int ntiles = N >> 7;

    cudaFuncSetAttribute(k_gemm, cudaFuncAttributeMaxDynamicSharedMemorySize, SMEM_BYTES);

    k_init<<<32, 256>>>(labw, N);
    k_norm<<<(N + 7) / 8, 256>>>(feats, labw, N);
    dim3 grid(ntiles, ntiles);
    k_gemm<<<grid, 256, SMEM_BYTES>>>(labw);
    k_final<<<1, 1024>>>(labw, (float*)d_out, N);
}

// round 6
// speedup vs baseline: 2.9299x; 2.9299x over previous
#include <cuda_runtime.h>
#include <cuda_bf16.h>
#include <stdint.h>
#include <math.h>

// SupConLoss fused, mma.sync (bf16 HMMA) version — tcgen05 unavailable on the
// harness's compute_103 PTX target.
//   k_norm: L2-normalize rows -> bf16, label histogram
//   k_gemm: 128x128 bf16 mma.sync tiles, fused exp/mask epilogue on fragments
//   k_final: scalar loss
// loss_i = log(S_i + 1e-9) - P_i / n_pos_i  (0 if n_pos_i == 0); loss = mean_i

#define MAXN 8192
#define D128 128
#define INV_T 10.0f

__device__ __nv_bfloat16 g_featsb[MAXN * D128];
__device__ float g_sumexp[MAXN];
__device__ float g_psum[MAXN];
__device__ int   g_labcnt[1024];
__device__ int   g_lab64;

__device__ __forceinline__ int load_lab(const int* labw, int i, int is64) {
    return labw[is64 ? (i << 1) : i];
}

__device__ __forceinline__ uint32_t smem_u32(const void* p) {
    uint32_t a;
    asm("{ .reg .u64 t; cvta.to.shared.u64 t, %1; cvt.u32.u64 %0, t; }" : "=r"(a) : "l"(p));
    return a;
}

__device__ __forceinline__ void ldsm4(uint32_t& r0, uint32_t& r1, uint32_t& r2,
                                      uint32_t& r3, uint32_t addr) {
    asm volatile("ldmatrix.sync.aligned.m8n8.x4.shared.b16 {%0,%1,%2,%3}, [%4];"
                 : "=r"(r0), "=r"(r1), "=r"(r2), "=r"(r3) : "r"(addr));
}

__device__ __forceinline__ void mma16816(float* d, uint32_t a0, uint32_t a1,
                                         uint32_t a2, uint32_t a3,
                                         uint32_t b0, uint32_t b1) {
    asm volatile(
        "mma.sync.aligned.m16n8k16.row.col.f32.bf16.bf16.f32 "
        "{%0,%1,%2,%3}, {%4,%5,%6,%7}, {%8,%9}, {%0,%1,%2,%3};"
        : "+f"(d[0]), "+f"(d[1]), "+f"(d[2]), "+f"(d[3])
        : "r"(a0), "r"(a1), "r"(a2), "r"(a3), "r"(b0), "r"(b1));
}

// ---------------------------------------------------------------------------
__global__ void k_init(const int* __restrict__ labw, int N) {
    int tid = blockIdx.x * blockDim.x + threadIdx.x;
    int stride = gridDim.x * blockDim.x;
    for (int i = tid; i < N; i += stride) { g_sumexp[i] = 0.0f; g_psum[i] = 0.0f; }
    for (int i = tid; i < 1024; i += stride) g_labcnt[i] = 0;
    if (blockIdx.x == 0 && threadIdx.x == 0) {
        int z = 0;
        #pragma unroll
        for (int i = 0; i < 32; ++i) z |= labw[2 * i + 1];
        g_lab64 = (z == 0) ? 1 : 0;
    }
}

// ---------------------------------------------------------------------------
__global__ void k_norm(const float* __restrict__ feats,
                       const int* __restrict__ labw, int N) {
    int row = blockIdx.x * 8 + (threadIdx.x >> 5);
    int lane = threadIdx.x & 31;
    if (row >= N) return;
    const float4 v = *(const float4*)(feats + row * D128 + (lane << 2));
    float ss = v.x * v.x + v.y * v.y + v.z * v.z + v.w * v.w;
    #pragma unroll
    for (int o = 16; o > 0; o >>= 1) ss += __shfl_xor_sync(0xFFFFFFFFu, ss, o);
    float inv = rsqrtf(ss);
    __nv_bfloat162 h0, h1;
    h0.x = __float2bfloat16_rn(v.x * inv); h0.y = __float2bfloat16_rn(v.y * inv);
    h1.x = __float2bfloat16_rn(v.z * inv); h1.y = __float2bfloat16_rn(v.w * inv);
    uint2 pk;
    pk.x = *(uint32_t*)&h0; pk.y = *(uint32_t*)&h1;
    *(uint2*)(g_featsb + row * D128 + (lane << 2)) = pk;
    if (lane == 0) atomicAdd(&g_labcnt[load_lab(labw, row, g_lab64) & 1023], 1);
}

// ---------------------------------------------------------------------------
// K2: 128x128 bf16 mma.sync tile + fused epilogue
// SMEM tiles: k-major bf16, row = 256B (16 chunks of 16B), chunk c stored at
// (c ^ (row & 7)) -> conflict-free STS (uint4) and ldmatrix.
// ---------------------------------------------------------------------------
#define SM_AS 0
#define SM_BS 32768
#define SM_LABA 65536
#define SM_LABB (65536 + 512)
#define SMEM_BYTES (65536 + 1024)

__global__ void __launch_bounds__(256, 2)
k_gemm(const int* __restrict__ labw) {
    extern __shared__ char smem[];
    int* labA = (int*)(smem + SM_LABA);
    int* labB = (int*)(smem + SM_LABB);

    const int tid = threadIdx.x;
    const int m0 = blockIdx.y << 7, n0 = blockIdx.x << 7;
    const int is64 = g_lab64;

    if (tid < 128) labA[tid] = load_lab(labw, m0 + tid, is64);
    else           labB[tid - 128] = load_lab(labw, n0 + tid - 128, is64);

    // Load A and B tiles: 128 rows x 16 chunks(16B) each, swizzled.
    #pragma unroll
    for (int it = 0; it < 8; ++it) {
        int idx = (it << 8) + tid;          // 0..2047
        int row = idx >> 4;
        int c   = idx & 15;
        uint32_t sw = (uint32_t)(row << 8) + (uint32_t)((c ^ (row & 7)) << 4);
        const uint4 va = *(const uint4*)(g_featsb + (m0 + row) * D128 + (c << 3));
        const uint4 vb = *(const uint4*)(g_featsb + (n0 + row) * D128 + (c << 3));
        *(uint4*)(smem + SM_AS + sw) = va;
        *(uint4*)(smem + SM_BS + sw) = vb;
    }
    __syncthreads();

    const int lane = tid & 31;
    const int warp = tid >> 5;
    const int mbase = (warp >> 1) << 5;     // 0,32,64,96
    const int nbase = (warp & 1) << 6;      // 0,64

    // ldmatrix row/base precompute
    const int arow = mbase + (lane & 15);                   // + im*16
    const int brow0 = nbase + (lane & 7) + ((lane >> 4) << 3); // + inp*16
    const int achunk_off = lane >> 4;                       // 0 or 1
    const int bchunk_off = (lane >> 3) & 1;

    uint32_t As = smem_u32(smem + SM_AS);
    uint32_t Bs = smem_u32(smem + SM_BS);

    float acc[2][8][4];
    #pragma unroll
    for (int im = 0; im < 2; ++im)
        #pragma unroll
        for (int in = 0; in < 8; ++in)
            #pragma unroll
            for (int u = 0; u < 4; ++u) acc[im][in][u] = 0.0f;

    #pragma unroll
    for (int ks = 0; ks < 8; ++ks) {
        uint32_t a[2][4];
        #pragma unroll
        for (int im = 0; im < 2; ++im) {
            int r = arow + (im << 4);
            int ch = (ks << 1) + achunk_off;
            uint32_t addr = As + (uint32_t)(r << 8) + (uint32_t)(((ch ^ (r & 7)) << 4));
            ldsm4(a[im][0], a[im][1], a[im][2], a[im][3], addr);
        }
        #pragma unroll
        for (int inp = 0; inp < 4; ++inp) {
            int r = brow0 + (inp << 4);
            int ch = (ks << 1) + bchunk_off;
            uint32_t addr = Bs + (uint32_t)(r << 8) + (uint32_t)(((ch ^ (r & 7)) << 4));
            uint32_t b00, b01, b10, b11;
            ldsm4(b00, b01, b10, b11, addr);
            mma16816(acc[0][2 * inp],     a[0][0], a[0][1], a[0][2], a[0][3], b00, b01);
            mma16816(acc[0][2 * inp + 1], a[0][0], a[0][1], a[0][2], a[0][3], b10, b11);
            mma16816(acc[1][2 * inp],     a[1][0], a[1][1], a[1][2], a[1][3], b00, b01);
            mma16816(acc[1][2 * inp + 1], a[1][0], a[1][1], a[1][2], a[1][3], b10, b11);
        }
    }

    // ---- fused epilogue on fragments ----
    // Thread owns rows mbase + im*16 + g4 (+8), cols nbase + in*8 + tc*2 (+1).
    const int g4 = lane >> 2, tc = lane & 3;
    float s[4], p[4];     // [im*2 + hi]
    #pragma unroll
    for (int u = 0; u < 4; ++u) { s[u] = 0.0f; p[u] = 0.0f; }

    #pragma unroll
    for (int im = 0; im < 2; ++im) {
        #pragma unroll
        for (int hi = 0; hi < 2; ++hi) {
            const int rloc = mbase + (im << 4) + g4 + (hi << 3);
            const int gi = m0 + rloc;
            const int ml = labA[rloc];
            float ls = 0.0f, lp = 0.0f;
            #pragma unroll
            for (int in = 0; in < 8; ++in) {
                const int cloc = nbase + (in << 3) + (tc << 1);
                #pragma unroll
                for (int u = 0; u < 2; ++u) {
                    float v = acc[im][in][(hi << 1) + u] * INV_T;
                    float e = __expf(v);
                    if (n0 + cloc + u != gi) {
                        ls += e;
                        if (labB[cloc + u] == ml) lp += v;
                    }
                }
            }
            s[(im << 1) + hi] = ls;
            p[(im << 1) + hi] = lp;
        }
    }
    // reduce over the 4 column lanes (same g4, tc 0..3)
    #pragma unroll
    for (int u = 0; u < 4; ++u) {
        s[u] += __shfl_xor_sync(0xFFFFFFFFu, s[u], 1);
        s[u] += __shfl_xor_sync(0xFFFFFFFFu, s[u], 2);
        p[u] += __shfl_xor_sync(0xFFFFFFFFu, p[u], 1);
        p[u] += __shfl_xor_sync(0xFFFFFFFFu, p[u], 2);
    }
    if (tc == 0) {
        #pragma unroll
        for (int u = 0; u < 4; ++u) {
            int rloc = mbase + ((u >> 1) << 4) + g4 + ((u & 1) << 3);
            atomicAdd(&g_sumexp[m0 + rloc], s[u]);
            atomicAdd(&g_psum[m0 + rloc], p[u]);
        }
    }
}

// ---------------------------------------------------------------------------
__global__ void k_final(const int* __restrict__ labw, float* __restrict__ out, int N) {
    __shared__ float wsum[32];
    const int tid = threadIdx.x;
    const int is64 = g_lab64;
    float local = 0.0f;
    for (int i = tid; i < N; i += blockDim.x) {
        int lab = load_lab(labw, i, is64) & 1023;
        int np = g_labcnt[lab] - 1;
        if (np > 0) {
            float L = logf(g_sumexp[i] + 1e-9f);
            local += L - g_psum[i] / (float)np;
        }
    }
    #pragma unroll
    for (int o = 16; o > 0; o >>= 1) local += __shfl_xor_sync(0xFFFFFFFFu, local, o);
    if ((tid & 31) == 0) wsum[tid >> 5] = local;
    __syncthreads();
    if (tid < 32) {
        float v = (tid < (blockDim.x >> 5)) ? wsum[tid] : 0.0f;
        #pragma unroll
        for (int o = 16; o > 0; o >>= 1) v += __shfl_xor_sync(0xFFFFFFFFu, v, o);
        if (tid == 0) out[0] = v / (float)N;
    }
}

// ---------------------------------------------------------------------------
extern "C" void kernel_launch(void* const* d_in, const int* in_sizes, int n_in,
                              void* d_out, int out_size) {
    const float* feats = (const float*)d_in[0];
    const int*   labw  = (const int*)d_in[1];
    const int N = in_sizes[1];
    const int ntiles = N >> 7;

    cudaFuncSetAttribute(k_gemm, cudaFuncAttributeMaxDynamicSharedMemorySize, SMEM_BYTES);

    k_init<<<32, 256>>>(labw, N);
    k_norm<<<(N + 7) / 8, 256>>>(feats, labw, N);
    dim3 grid(ntiles, ntiles);
    k_gemm<<<grid, 256, SMEM_BYTES>>>(labw);
    k_final<<<1, 1024>>>(labw, (float*)d_out, N);
}

// round 7
// speedup vs baseline: 4.4570x; 1.5212x over previous
#include <cuda_runtime.h>
#include <cuda_bf16.h>
#include <stdint.h>
#include <math.h>

// SupConLoss fused, mma.sync bf16, TRIANGULAR tiling (sim symmetric):
//   off-diagonal tile (by<bx) contributes row sums (rows m0..) AND col sums
//   (rows n0.. by symmetry). k_final parallelized across 32 blocks.
// loss_i = log(S_i + 1e-9) - P_i / n_pos_i  (0 if n_pos_i == 0); loss = mean_i

#define MAXN 8192
#define D128 128
#define INV_T 10.0f

__device__ __nv_bfloat16 g_featsb[MAXN * D128];
__device__ float g_sumexp[MAXN];
__device__ float g_psum[MAXN];
__device__ int   g_labcnt[1024];
__device__ int   g_lab64;

__device__ __forceinline__ int load_lab(const int* labw, int i, int is64) {
    return labw[is64 ? (i << 1) : i];
}

__device__ __forceinline__ uint32_t smem_u32(const void* p) {
    uint32_t a;
    asm("{ .reg .u64 t; cvta.to.shared.u64 t, %1; cvt.u32.u64 %0, t; }" : "=r"(a) : "l"(p));
    return a;
}

__device__ __forceinline__ void ldsm4(uint32_t& r0, uint32_t& r1, uint32_t& r2,
                                      uint32_t& r3, uint32_t addr) {
    asm volatile("ldmatrix.sync.aligned.m8n8.x4.shared.b16 {%0,%1,%2,%3}, [%4];"
                 : "=r"(r0), "=r"(r1), "=r"(r2), "=r"(r3) : "r"(addr));
}

__device__ __forceinline__ void mma16816(float* d, uint32_t a0, uint32_t a1,
                                         uint32_t a2, uint32_t a3,
                                         uint32_t b0, uint32_t b1) {
    asm volatile(
        "mma.sync.aligned.m16n8k16.row.col.f32.bf16.bf16.f32 "
        "{%0,%1,%2,%3}, {%4,%5,%6,%7}, {%8,%9}, {%0,%1,%2,%3};"
        : "+f"(d[0]), "+f"(d[1]), "+f"(d[2]), "+f"(d[3])
        : "r"(a0), "r"(a1), "r"(a2), "r"(a3), "r"(b0), "r"(b1));
}

// ---------------------------------------------------------------------------
__global__ void k_init(const int* __restrict__ labw, float* __restrict__ out, int N) {
    int tid = blockIdx.x * blockDim.x + threadIdx.x;
    int stride = gridDim.x * blockDim.x;
    for (int i = tid; i < N; i += stride) { g_sumexp[i] = 0.0f; g_psum[i] = 0.0f; }
    for (int i = tid; i < 1024; i += stride) g_labcnt[i] = 0;
    if (blockIdx.x == 0 && threadIdx.x == 0) {
        out[0] = 0.0f;
        int z = 0;
        #pragma unroll
        for (int i = 0; i < 32; ++i) z |= labw[2 * i + 1];
        g_lab64 = (z == 0) ? 1 : 0;
    }
}

// ---------------------------------------------------------------------------
__global__ void k_norm(const float* __restrict__ feats,
                       const int* __restrict__ labw, int N) {
    int row = blockIdx.x * 8 + (threadIdx.x >> 5);
    int lane = threadIdx.x & 31;
    if (row >= N) return;
    const float4 v = *(const float4*)(feats + row * D128 + (lane << 2));
    float ss = v.x * v.x + v.y * v.y + v.z * v.z + v.w * v.w;
    #pragma unroll
    for (int o = 16; o > 0; o >>= 1) ss += __shfl_xor_sync(0xFFFFFFFFu, ss, o);
    float inv = rsqrtf(ss);
    __nv_bfloat162 h0, h1;
    h0.x = __float2bfloat16_rn(v.x * inv); h0.y = __float2bfloat16_rn(v.y * inv);
    h1.x = __float2bfloat16_rn(v.z * inv); h1.y = __float2bfloat16_rn(v.w * inv);
    uint2 pk;
    pk.x = *(uint32_t*)&h0; pk.y = *(uint32_t*)&h1;
    *(uint2*)(g_featsb + row * D128 + (lane << 2)) = pk;
    if (lane == 0) atomicAdd(&g_labcnt[load_lab(labw, row, g_lab64) & 1023], 1);
}

// ---------------------------------------------------------------------------
// K2: 128x128 bf16 mma.sync tile + fused epilogue, triangular grid.
// SMEM tiles: k-major bf16, row = 256B (16 chunks of 16B), chunk c at c^(row&7).
// ---------------------------------------------------------------------------
#define SM_AS 0
#define SM_BS 32768
#define SM_LABA 65536
#define SM_LABB (65536 + 512)
#define SMEM_BYTES (65536 + 1024)

__global__ void __launch_bounds__(256, 2)
k_gemm(const int* __restrict__ labw) {
    extern __shared__ char smem[];
    int* labA = (int*)(smem + SM_LABA);
    int* labB = (int*)(smem + SM_LABB);

    const int tid = threadIdx.x;
    // triangular decode: bid -> (bx, by) with by <= bx
    int bid = blockIdx.x;
    int bx = (int)((sqrtf(8.0f * (float)bid + 1.0f) - 1.0f) * 0.5f);
    while ((bx + 1) * (bx + 2) / 2 <= bid) bx++;
    while (bx * (bx + 1) / 2 > bid) bx--;
    const int by = bid - bx * (bx + 1) / 2;

    const int m0 = by << 7, n0 = bx << 7;
    const bool offdiag = (bx != by);
    const int is64 = g_lab64;

    if (tid < 128) labA[tid] = load_lab(labw, m0 + tid, is64);
    else           labB[tid - 128] = load_lab(labw, n0 + tid - 128, is64);

    #pragma unroll
    for (int it = 0; it < 8; ++it) {
        int idx = (it << 8) + tid;          // 0..2047
        int row = idx >> 4;
        int c   = idx & 15;
        uint32_t sw = (uint32_t)(row << 8) + (uint32_t)((c ^ (row & 7)) << 4);
        const uint4 va = *(const uint4*)(g_featsb + (m0 + row) * D128 + (c << 3));
        const uint4 vb = *(const uint4*)(g_featsb + (n0 + row) * D128 + (c << 3));
        *(uint4*)(smem + SM_AS + sw) = va;
        *(uint4*)(smem + SM_BS + sw) = vb;
    }
    __syncthreads();

    const int lane = tid & 31;
    const int warp = tid >> 5;
    const int mbase = (warp >> 1) << 5;     // 0,32,64,96
    const int nbase = (warp & 1) << 6;      // 0,64

    const int arow = mbase + (lane & 15);
    const int brow0 = nbase + (lane & 7) + ((lane >> 4) << 3);
    const int achunk_off = lane >> 4;
    const int bchunk_off = (lane >> 3) & 1;

    uint32_t As = smem_u32(smem + SM_AS);
    uint32_t Bs = smem_u32(smem + SM_BS);

    float acc[2][8][4];
    #pragma unroll
    for (int im = 0; im < 2; ++im)
        #pragma unroll
        for (int in = 0; in < 8; ++in)
            #pragma unroll
            for (int u = 0; u < 4; ++u) acc[im][in][u] = 0.0f;

    #pragma unroll
    for (int ks = 0; ks < 8; ++ks) {
        uint32_t a[2][4];
        #pragma unroll
        for (int im = 0; im < 2; ++im) {
            int r = arow + (im << 4);
            int ch = (ks << 1) + achunk_off;
            uint32_t addr = As + (uint32_t)(r << 8) + (uint32_t)(((ch ^ (r & 7)) << 4));
            ldsm4(a[im][0], a[im][1], a[im][2], a[im][3], addr);
        }
        #pragma unroll
        for (int inp = 0; inp < 4; ++inp) {
            int r = brow0 + (inp << 4);
            int ch = (ks << 1) + bchunk_off;
            uint32_t addr = Bs + (uint32_t)(r << 8) + (uint32_t)(((ch ^ (r & 7)) << 4));
            uint32_t b00, b01, b10, b11;
            ldsm4(b00, b01, b10, b11, addr);
            mma16816(acc[0][2 * inp],     a[0][0], a[0][1], a[0][2], a[0][3], b00, b01);
            mma16816(acc[0][2 * inp + 1], a[0][0], a[0][1], a[0][2], a[0][3], b10, b11);
            mma16816(acc[1][2 * inp],     a[1][0], a[1][1], a[1][2], a[1][3], b00, b01);
            mma16816(acc[1][2 * inp + 1], a[1][0], a[1][1], a[1][2], a[1][3], b10, b11);
        }
    }

    // ---- fused epilogue ----
    // Thread owns rows mbase+im*16+g4(+8), cols nbase+in*8+tc*2(+1).
    const int g4 = lane >> 2, tc = lane & 3;
    float s[4], p[4];
    #pragma unroll
    for (int u = 0; u < 4; ++u) { s[u] = 0.0f; p[u] = 0.0f; }

    // col-partial staging buffers reuse the A tile region (mainloop done)
    float* cs_buf = (float*)(smem + SM_AS);          // [4][128]
    float* cp_buf = (float*)(smem + SM_AS + 2048);   // [4][128]
    __syncthreads();   // all ldmatrix reads complete before smem reuse

    #pragma unroll
    for (int in = 0; in < 8; ++in) {
        const int cbase = nbase + (in << 3) + (tc << 1);
        float cs0 = 0.0f, cs1 = 0.0f, cp0 = 0.0f, cp1 = 0.0f;
        const int lb0 = labB[cbase], lb1 = labB[cbase + 1];
        #pragma unroll
        for (int im = 0; im < 2; ++im) {
            #pragma unroll
            for (int hi = 0; hi < 2; ++hi) {
                const int rloc = mbase + (im << 4) + g4 + (hi << 3);
                const int gi = m0 + rloc;
                const int ml = labA[rloc];
                const int su = (im << 1) + hi;

                float v0 = acc[im][in][(hi << 1)] * INV_T;
                float e0 = __expf(v0);
                if (n0 + cbase != gi) {
                    s[su] += e0; cs0 += e0;
                    if (lb0 == ml) { p[su] += v0; cp0 += v0; }
                }
                float v1 = acc[im][in][(hi << 1) + 1] * INV_T;
                float e1 = __expf(v1);
                if (n0 + cbase + 1 != gi) {
                    s[su] += e1; cs1 += e1;
                    if (lb1 == ml) { p[su] += v1; cp1 += v1; }
                }
            }
        }
        if (offdiag) {
            #pragma unroll
            for (int o = 4; o < 32; o <<= 1) {
                cs0 += __shfl_xor_sync(0xFFFFFFFFu, cs0, o);
                cs1 += __shfl_xor_sync(0xFFFFFFFFu, cs1, o);
                cp0 += __shfl_xor_sync(0xFFFFFFFFu, cp0, o);
                cp1 += __shfl_xor_sync(0xFFFFFFFFu, cp1, o);
            }
            if (g4 == 0) {
                int kk = warp >> 1;
                cs_buf[kk * 128 + cbase] = cs0;
                cs_buf[kk * 128 + cbase + 1] = cs1;
                cp_buf[kk * 128 + cbase] = cp0;
                cp_buf[kk * 128 + cbase + 1] = cp1;
            }
        }
    }

    // row sums: reduce over the 4 column lanes
    #pragma unroll
    for (int u = 0; u < 4; ++u) {
        s[u] += __shfl_xor_sync(0xFFFFFFFFu, s[u], 1);
        s[u] += __shfl_xor_sync(0xFFFFFFFFu, s[u], 2);
        p[u] += __shfl_xor_sync(0xFFFFFFFFu, p[u], 1);
        p[u] += __shfl_xor_sync(0xFFFFFFFFu, p[u], 2);
    }
    if (tc == 0) {
        #pragma unroll
        for (int u = 0; u < 4; ++u) {
            int rloc = mbase + ((u >> 1) << 4) + g4 + ((u & 1) << 3);
            atomicAdd(&g_sumexp[m0 + rloc], s[u]);
            atomicAdd(&g_psum[m0 + rloc], p[u]);
        }
    }

    if (offdiag) {   // symmetric: cols of this tile are rows n0+j
        __syncthreads();
        if (tid < 128) {
            float S = 0.0f, P = 0.0f;
            #pragma unroll
            for (int kk = 0; kk < 4; ++kk) {
                S += cs_buf[kk * 128 + tid];
                P += cp_buf[kk * 128 + tid];
            }
            atomicAdd(&g_sumexp[n0 + tid], S);
            atomicAdd(&g_psum[n0 + tid], P);
        }
    }
}

// ---------------------------------------------------------------------------
__global__ void k_final(const int* __restrict__ labw, float* __restrict__ out, int N) {
    __shared__ float wsum[8];
    const int tid = threadIdx.x;
    const int i = blockIdx.x * blockDim.x + tid;
    const int is64 = g_lab64;
    float local = 0.0f;
    if (i < N) {
        int lab = load_lab(labw, i, is64) & 1023;
        int np = g_labcnt[lab] - 1;
        if (np > 0) {
            float L = logf(g_sumexp[i] + 1e-9f);
            local = L - g_psum[i] / (float)np;
        }
    }
    #pragma unroll
    for (int o = 16; o > 0; o >>= 1) local += __shfl_xor_sync(0xFFFFFFFFu, local, o);
    if ((tid & 31) == 0) wsum[tid >> 5] = local;
    __syncthreads();
    if (tid < 32) {
        float v = (tid < (blockDim.x >> 5)) ? wsum[tid] : 0.0f;
        #pragma unroll
        for (int o = 4; o > 0; o >>= 1) v += __shfl_xor_sync(0xFFFFFFFFu, v, o);
        if (tid == 0) atomicAdd(out, v / (float)N);
    }
}

// ---------------------------------------------------------------------------
extern "C" void kernel_launch(void* const* d_in, const int* in_sizes, int n_in,
                              void* d_out, int out_size) {
    const float* feats = (const float*)d_in[0];
    const int*   labw  = (const int*)d_in[1];
    const int N = in_sizes[1];
    const int ntiles = N >> 7;
    const int ntri = ntiles * (ntiles + 1) / 2;

    cudaFuncSetAttribute(k_gemm, cudaFuncAttributeMaxDynamicSharedMemorySize, SMEM_BYTES);

    k_init<<<32, 256>>>(labw, (float*)d_out, N);
    k_norm<<<(N + 7) / 8, 256>>>(feats, labw, N);
    k_gemm<<<ntri, 256, SMEM_BYTES>>>(labw);
    k_final<<<(N + 255) / 256, 256>>>(labw, (float*)d_out, N);
}

// round 9
// speedup vs baseline: 4.6832x; 1.0507x over previous
#include <cuda_runtime.h>
#include <cuda_bf16.h>
#include <stdint.h>
#include <math.h>

// SupConLoss fused, mma.sync bf16, triangular tiling, 64x64 warp tiles.
// loss_i = log(S_i + 1e-9) - P_i / n_pos_i  (0 if n_pos_i == 0); loss = mean_i

#define MAXN 8192
#define D128 128
#define INV_T 10.0f

__device__ __nv_bfloat16 g_featsb[MAXN * D128];
__device__ float g_sumexp[MAXN];
__device__ float g_psum[MAXN];
__device__ int   g_labcnt[1024];
__device__ int   g_lab64;

__device__ __forceinline__ int load_lab(const int* labw, int i, int is64) {
    return labw[is64 ? (i << 1) : i];
}

__device__ __forceinline__ uint32_t smem_u32(const void* p) {
    uint32_t a;
    asm("{ .reg .u64 t; cvta.to.shared.u64 t, %1; cvt.u32.u64 %0, t; }" : "=r"(a) : "l"(p));
    return a;
}

__device__ __forceinline__ void ldsm4(uint32_t& r0, uint32_t& r1, uint32_t& r2,
                                      uint32_t& r3, uint32_t addr) {
    asm volatile("ldmatrix.sync.aligned.m8n8.x4.shared.b16 {%0,%1,%2,%3}, [%4];"
                 : "=r"(r0), "=r"(r1), "=r"(r2), "=r"(r3) : "r"(addr));
}

__device__ __forceinline__ void mma16816(float* d, const uint32_t* a,
                                         uint32_t b0, uint32_t b1) {
    asm volatile(
        "mma.sync.aligned.m16n8k16.row.col.f32.bf16.bf16.f32 "
        "{%0,%1,%2,%3}, {%4,%5,%6,%7}, {%8,%9}, {%0,%1,%2,%3};"
        : "+f"(d[0]), "+f"(d[1]), "+f"(d[2]), "+f"(d[3])
        : "r"(a[0]), "r"(a[1]), "r"(a[2]), "r"(a[3]), "r"(b0), "r"(b1));
}

// ---------------------------------------------------------------------------
// K0: one block — zero labcnt, zero out, detect label dtype
// ---------------------------------------------------------------------------
__global__ void k_init(const int* __restrict__ labw, float* __restrict__ out) {
    int tid = threadIdx.x;
    for (int i = tid; i < 1024; i += 256) g_labcnt[i] = 0;
    if (tid == 0) {
        out[0] = 0.0f;
        int z = 0;
        #pragma unroll
        for (int i = 0; i < 32; ++i) z |= labw[2 * i + 1];
        g_lab64 = (z == 0) ? 1 : 0;
    }
}

// ---------------------------------------------------------------------------
// K1: L2-normalize rows -> bf16, histogram, zero per-row accumulators
// ---------------------------------------------------------------------------
__global__ void k_norm(const float* __restrict__ feats,
                       const int* __restrict__ labw, int N) {
    int row = blockIdx.x * 8 + (threadIdx.x >> 5);
    int lane = threadIdx.x & 31;
    if (row >= N) return;
    // per-warp label dtype detect (no dependency on k_init ordering)
    int hw = labw[2 * lane + 1];
    int is64 = __any_sync(0xFFFFFFFFu, hw != 0) ? 0 : 1;

    const float4 v = *(const float4*)(feats + row * D128 + (lane << 2));
    float ss = v.x * v.x + v.y * v.y + v.z * v.z + v.w * v.w;
    #pragma unroll
    for (int o = 16; o > 0; o >>= 1) ss += __shfl_xor_sync(0xFFFFFFFFu, ss, o);
    float inv = rsqrtf(ss);
    __nv_bfloat162 h0, h1;
    h0.x = __float2bfloat16_rn(v.x * inv); h0.y = __float2bfloat16_rn(v.y * inv);
    h1.x = __float2bfloat16_rn(v.z * inv); h1.y = __float2bfloat16_rn(v.w * inv);
    uint2 pk;
    pk.x = *(uint32_t*)&h0; pk.y = *(uint32_t*)&h1;
    *(uint2*)(g_featsb + row * D128 + (lane << 2)) = pk;
    if (lane == 0) atomicAdd(&g_labcnt[load_lab(labw, row, is64) & 1023], 1);
    else if (lane == 1) g_sumexp[row] = 0.0f;
    else if (lane == 2) g_psum[row] = 0.0f;
}

// ---------------------------------------------------------------------------
// K2: 128x128 tile, 4 warps of 64x64, bf16 mma.sync, fused epilogue.
// SMEM tiles: k-major bf16, row = 256B (16 chunks of 16B), chunk c at c^(row&7).
// ---------------------------------------------------------------------------
#define SM_AS 0
#define SM_BS 32768
#define SM_LABA 65536
#define SM_LABB (65536 + 512)
#define SMEM_BYTES (65536 + 1024)

__global__ void __launch_bounds__(128, 2)
k_gemm(const int* __restrict__ labw) {
    extern __shared__ char smem[];
    int* labA = (int*)(smem + SM_LABA);
    int* labB = (int*)(smem + SM_LABB);

    const int tid = threadIdx.x;
    // triangular decode: bid -> (bx, by) with by <= bx
    int bid = blockIdx.x;
    int bx = (int)((sqrtf(8.0f * (float)bid + 1.0f) - 1.0f) * 0.5f);
    while ((bx + 1) * (bx + 2) / 2 <= bid) bx++;
    while (bx * (bx + 1) / 2 > bid) bx--;
    const int by = bid - bx * (bx + 1) / 2;

    const int m0 = by << 7, n0 = bx << 7;
    const bool offdiag = (bx != by);
    const int is64 = g_lab64;

    if (tid < 128) {
        labA[tid] = load_lab(labw, m0 + tid, is64);
        labB[tid] = load_lab(labw, n0 + tid, is64);
    }

    #pragma unroll
    for (int it = 0; it < 16; ++it) {
        int idx = (it << 7) + tid;          // 0..2047
        int row = idx >> 4;
        int c   = idx & 15;
        uint32_t sw = (uint32_t)(row << 8) + (uint32_t)((c ^ (row & 7)) << 4);
        const uint4 va = *(const uint4*)(g_featsb + (m0 + row) * D128 + (c << 3));
        const uint4 vb = *(const uint4*)(g_featsb + (n0 + row) * D128 + (c << 3));
        *(uint4*)(smem + SM_AS + sw) = va;
        *(uint4*)(smem + SM_BS + sw) = vb;
    }
    __syncthreads();

    const int lane = tid & 31;
    const int warp = tid >> 5;
    const int mbase = (warp >> 1) << 6;     // 0,64
    const int nbase = (warp & 1) << 6;      // 0,64

    const int arow = mbase + (lane & 15);
    const int brow0 = nbase + (lane & 7) + ((lane >> 4) << 3);
    const int achunk_off = lane >> 4;
    const int bchunk_off = (lane >> 3) & 1;

    uint32_t As = smem_u32(smem + SM_AS);
    uint32_t Bs = smem_u32(smem + SM_BS);

    float acc[4][8][4];
    #pragma unroll
    for (int im = 0; im < 4; ++im)
        #pragma unroll
        for (int in = 0; in < 8; ++in)
            #pragma unroll
            for (int u = 0; u < 4; ++u) acc[im][in][u] = 0.0f;

    #pragma unroll
    for (int ks = 0; ks < 8; ++ks) {
        uint32_t a[4][4];
        #pragma unroll
        for (int im = 0; im < 4; ++im) {
            int r = arow + (im << 4);
            int ch = (ks << 1) + achunk_off;
            uint32_t addr = As + (uint32_t)(r << 8) + (uint32_t)(((ch ^ (r & 7)) << 4));
            ldsm4(a[im][0], a[im][1], a[im][2], a[im][3], addr);
        }
        #pragma unroll
        for (int inp = 0; inp < 4; ++inp) {
            int r = brow0 + (inp << 4);
            int ch = (ks << 1) + bchunk_off;
            uint32_t addr = Bs + (uint32_t)(r << 8) + (uint32_t)(((ch ^ (r & 7)) << 4));
            uint32_t b00, b01, b10, b11;
            ldsm4(b00, b01, b10, b11, addr);
            #pragma unroll
            for (int im = 0; im < 4; ++im) {
                mma16816(acc[im][2 * inp],     a[im], b00, b01);
                mma16816(acc[im][2 * inp + 1], a[im], b10, b11);
            }
        }
    }

    // ---- fused epilogue ----
    // Thread owns rows mbase+im*16+g4(+8), cols nbase+in*8+tc*2(+1).
    const int g4 = lane >> 2, tc = lane & 3;
    float s[8], p[8];
    #pragma unroll
    for (int u = 0; u < 8; ++u) { s[u] = 0.0f; p[u] = 0.0f; }

    float* cs_buf = (float*)(smem + SM_AS);          // [2][128]
    float* cp_buf = (float*)(smem + SM_AS + 1024);   // [2][128]
    __syncthreads();   // all ldmatrix reads complete before smem reuse

    if (offdiag) {
        #pragma unroll
        for (int in = 0; in < 8; ++in) {
            const int cbase = nbase + (in << 3) + (tc << 1);
            float cs0 = 0.0f, cs1 = 0.0f, cp0 = 0.0f, cp1 = 0.0f;
            const int lb0 = labB[cbase], lb1 = labB[cbase + 1];
            #pragma unroll
            for (int im = 0; im < 4; ++im) {
                #pragma unroll
                for (int hi = 0; hi < 2; ++hi) {
                    const int rloc = mbase + (im << 4) + g4 + (hi << 3);
                    const int ml = labA[rloc];
                    const int su = (im << 1) + hi;
                    float v0 = acc[im][in][(hi << 1)] * INV_T;
                    float e0 = __expf(v0);
                    s[su] += e0; cs0 += e0;
                    if (lb0 == ml) { p[su] += v0; cp0 += v0; }
                    float v1 = acc[im][in][(hi << 1) + 1] * INV_T;
                    float e1 = __expf(v1);
                    s[su] += e1; cs1 += e1;
                    if (lb1 == ml) { p[su] += v1; cp1 += v1; }
                }
            }
            #pragma unroll
            for (int o = 4; o < 32; o <<= 1) {
                cs0 += __shfl_xor_sync(0xFFFFFFFFu, cs0, o);
                cs1 += __shfl_xor_sync(0xFFFFFFFFu, cs1, o);
                cp0 += __shfl_xor_sync(0xFFFFFFFFu, cp0, o);
                cp1 += __shfl_xor_sync(0xFFFFFFFFu, cp1, o);
            }
            if (g4 == 0) {
                int kk = warp >> 1;
                cs_buf[kk * 128 + cbase] = cs0;
                cs_buf[kk * 128 + cbase + 1] = cs1;
                cp_buf[kk * 128 + cbase] = cp0;
                cp_buf[kk * 128 + cbase + 1] = cp1;
            }
        }
    } else {
        #pragma unroll
        for (int in = 0; in < 8; ++in) {
            const int cbase = nbase + (in << 3) + (tc << 1);
            const int lb0 = labB[cbase], lb1 = labB[cbase + 1];
            #pragma unroll
            for (int im = 0; im < 4; ++im) {
                #pragma unroll
                for (int hi = 0; hi < 2; ++hi) {
                    const int rloc = mbase + (im << 4) + g4 + (hi << 3);
                    const int ml = labA[rloc];
                    const int su = (im << 1) + hi;
                    float v0 = acc[im][in][(hi << 1)] * INV_T;
                    float e0 = __expf(v0);
                    if (cbase != rloc) {
                        s[su] += e0;
                        if (lb0 == ml) p[su] += v0;
                    }
                    float v1 = acc[im][in][(hi << 1) + 1] * INV_T;
                    float e1 = __expf(v1);
                    if (cbase + 1 != rloc) {
                        s[su] += e1;
                        if (lb1 == ml) p[su] += v1;
                    }
                }
            }
        }
    }

    // row sums: reduce over the 4 column lanes
    #pragma unroll
    for (int u = 0; u < 8; ++u) {
        s[u] += __shfl_xor_sync(0xFFFFFFFFu, s[u], 1);
        s[u] += __shfl_xor_sync(0xFFFFFFFFu, s[u], 2);
        p[u] += __shfl_xor_sync(0xFFFFFFFFu, p[u], 1);
        p[u] += __shfl_xor_sync(0xFFFFFFFFu, p[u], 2);
    }
    if (tc == 0) {
        #pragma unroll
        for (int u = 0; u < 8; ++u) {
            int rloc = mbase + ((u >> 1) << 4) + g4 + ((u & 1) << 3);
            atomicAdd(&g_sumexp[m0 + rloc], s[u]);
            atomicAdd(&g_psum[m0 + rloc], p[u]);
        }
    }

    if (offdiag) {   // symmetric: cols of this tile are rows n0+j
        __syncthreads();
        if (tid < 128) {
            float S = cs_buf[tid] + cs_buf[128 + tid];
            float P = cp_buf[tid] + cp_buf[128 + tid];
            atomicAdd(&g_sumexp[n0 + tid], S);
            atomicAdd(&g_psum[n0 + tid], P);
        }
    }
}

// ---------------------------------------------------------------------------
__global__ void k_final(const int* __restrict__ labw, float* __restrict__ out, int N) {
    __shared__ float wsum[8];
    const int tid = threadIdx.x;
    const int i = blockIdx.x * blockDim.x + tid;
    const int is64 = g_lab64;
    float local = 0.0f;
    if (i < N) {
        int lab = load_lab(labw, i, is64) & 1023;
        int np = g_labcnt[lab] - 1;
        if (np > 0) {
            float L = logf(g_sumexp[i] + 1e-9f);
            local = L - g_psum[i] / (float)np;
        }
    }
    #pragma unroll
    for (int o = 16; o > 0; o >>= 1) local += __shfl_xor_sync(0xFFFFFFFFu, local, o);
    if ((tid & 31) == 0) wsum[tid >> 5] = local;
    __syncthreads();
    if (tid < 32) {
        float v = (tid < (blockDim.x >> 5)) ? wsum[tid] : 0.0f;
        #pragma unroll
        for (int o = 4; o > 0; o >>= 1) v += __shfl_xor_sync(0xFFFFFFFFu, v, o);
        if (tid == 0) atomicAdd(out, v / (float)N);
    }
}

// ---------------------------------------------------------------------------
extern "C" void kernel_launch(void* const* d_in, const int* in_sizes, int n_in,
                              void* d_out, int out_size) {
    const float* feats = (const float*)d_in[0];
    const int*   labw  = (const int*)d_in[1];
    const int N = in_sizes[1];
    const int ntiles = N >> 7;
    const int ntri = ntiles * (ntiles + 1) / 2;

    cudaFuncSetAttribute(k_gemm, cudaFuncAttributeMaxDynamicSharedMemorySize, SMEM_BYTES);

    k_init<<<1, 256>>>(labw, (float*)d_out);
    k_norm<<<(N + 7) / 8, 256>>>(feats, labw, N);
    k_gemm<<<ntri, 128, SMEM_BYTES>>>(labw);
    k_final<<<(N + 255) / 256, 256>>>(labw, (float*)d_out, N);
}